// round 1
// baseline (speedup 1.0000x reference)
#include <cuda_runtime.h>
#include <cstdint>
#include <cstddef>

#define NB      64
#define NPRED   100800
#define KDET    512
#define CAP     8192
#define SEL_CAP 2048
#define CONF_T  0.7f
#define IOU_T   0.45f

// Global scratch (static __device__ arrays: allowed; no allocation).
__device__ float g_sc[NB][CAP];
__device__ int   g_ix[NB][CAP];
__device__ int   g_cnt[NB];     // zero-initialized at module load; reset by nms_kernel

// ---------------------------------------------------------------------------
// Kernel 1: score + warp-aggregated compaction.
// One thread per candidate. NPRED % 32 == 0 so a warp never straddles batches.
// ---------------------------------------------------------------------------
__global__ void score_compact_kernel(const float* __restrict__ pred) {
    int c = blockIdx.x * blockDim.x + threadIdx.x;     // grid sized exactly NB*NPRED
    int b = c / NPRED;
    int n = c - b * NPRED;
    const float* row = pred + (size_t)c * 9;
    float conf = __fmul_rn(row[4], row[5]);            // obj * cls (exact match w/ ref)
    bool pos = conf > CONF_T;
    unsigned m = __ballot_sync(0xffffffffu, pos);
    if (m) {
        int lane   = threadIdx.x & 31;
        int leader = __ffs(m) - 1;
        int base;
        if (lane == leader) base = atomicAdd(&g_cnt[b], __popc(m));
        base = __shfl_sync(0xffffffffu, base, leader);
        if (pos) {
            int p = base + __popc(m & ((1u << lane) - 1u));
            if (p < CAP) { g_sc[b][p] = conf; g_ix[b][p] = n; }
        }
    }
}

// ---------------------------------------------------------------------------
// Kernel 2: per-batch select + sort + IoU mask + greedy NMS + write.
// ---------------------------------------------------------------------------
struct SmemB {
    float    sel_sc[SEL_CAP];     // 8 KB
    int      sel_ix[SEL_CAP];     // 8 KB
    float4   boxes[KDET];         // 8 KB
    float    area[KDET];          // 2 KB
    unsigned mask[KDET * 16];     // 32 KB   suppression bitmask rows
    int      hist[1024];          // 4 KB    histogram / suffix sums
    unsigned removed[16];         // 64 B    (16B-aligned by construction)
    int      selCnt;
    int      b1;
};

__global__ __launch_bounds__(1024, 1)
void nms_kernel(const float* __restrict__ pred, float* __restrict__ out) {
    extern __shared__ SmemB s_[];
    SmemB& S = s_[0];
    const int tid = threadIdx.x;
    const int b   = blockIdx.x;

    int cnt = g_cnt[b];
    if (cnt > CAP) cnt = CAP;

    // ---- Phase 1: histogram of score bits [22:13] (exponent fixed in (0.7,1)) ----
    S.hist[tid] = 0;                       // blockDim == 1024 exactly
    if (tid == 0) { S.selCnt = 0; S.b1 = -1; }
    __syncthreads();
    for (int e = tid; e < cnt; e += 1024) {
        unsigned u = __float_as_uint(g_sc[b][e]);
        atomicAdd(&S.hist[(u >> 13) & 1023], 1);
    }
    __syncthreads();

    // ---- Phase 2: suffix sum (Hillis-Steele) + boundary-bin search ----
    for (int d = 1; d < 1024; d <<= 1) {
        int v = (tid + d < 1024) ? S.hist[tid + d] : 0;
        __syncthreads();
        S.hist[tid] += v;
        __syncthreads();
    }
    int target = (cnt < KDET) ? cnt : KDET;
    if (S.hist[tid] >= target) atomicMax(&S.b1, tid);
    __syncthreads();
    int b1 = S.b1;

    // ---- Phase 3: collect candidates in bins >= b1 (~ target + epsilon) ----
    for (int e = tid; e < cnt; e += 1024) {
        float sc = g_sc[b][e];
        unsigned u = __float_as_uint(sc);
        if ((int)((u >> 13) & 1023) >= b1) {
            int p = atomicAdd(&S.selCnt, 1);
            if (p < SEL_CAP) { S.sel_sc[p] = sc; S.sel_ix[p] = g_ix[b][e]; }
        }
    }
    __syncthreads();
    int selN = S.selCnt; if (selN > SEL_CAP) selN = SEL_CAP;
    for (int t = tid; t < SEL_CAP; t += 1024)
        if (t >= selN) { S.sel_sc[t] = -1.0f; S.sel_ix[t] = 0x7fffffff; }
    __syncthreads();

    // ---- Phase 4: bitonic sort of 2048 (score desc, idx asc — matches lax.top_k) ----
    for (int k = 2; k <= SEL_CAP; k <<= 1) {
        for (int j = k >> 1; j > 0; j >>= 1) {
            for (int t = tid; t < SEL_CAP; t += 1024) {
                int p = t ^ j;
                if (p > t) {
                    float s1 = S.sel_sc[t], s2 = S.sel_sc[p];
                    int   i1 = S.sel_ix[t], i2 = S.sel_ix[p];
                    bool t_better = (s1 > s2) || (s1 == s2 && i1 < i2);
                    if (t_better != ((t & k) == 0)) {
                        S.sel_sc[t] = s2; S.sel_sc[p] = s1;
                        S.sel_ix[t] = i2; S.sel_ix[p] = i1;
                    }
                }
            }
            __syncthreads();
        }
    }

    // ---- Phase 5: gather top-512 rows, build xyxy boxes + areas ----
    if (tid < KDET) {
        float sc = S.sel_sc[tid];
        float4 bx = make_float4(0.f, 0.f, 0.f, 0.f);
        float  ar = 0.f;
        if (sc > CONF_T) {
            const float* r = pred + ((size_t)b * NPRED + S.sel_ix[tid]) * 9;
            float cx = r[0], cy = r[1];
            float hw = __fmul_rn(r[2], 0.5f);   // exact; FMA-invariant below
            float hh = __fmul_rn(r[3], 0.5f);
            bx.x = __fsub_rn(cx, hw); bx.y = __fsub_rn(cy, hh);
            bx.z = __fadd_rn(cx, hw); bx.w = __fadd_rn(cy, hh);
            ar = __fmul_rn(__fsub_rn(bx.z, bx.x), __fsub_rn(bx.w, bx.y));
        }
        S.boxes[tid] = bx;
        S.area[tid]  = ar;
        // removed init: invalid (score <= thr or padding) slots start suppressed
        bool valid = sc > CONF_T;
        unsigned bal = __ballot_sync(0xffffffffu, valid);
        if ((tid & 31) == 0) S.removed[tid >> 5] = ~bal;
    }
    __syncthreads();

    // ---- Phase 6: upper-triangle IoU suppression bitmask (iou > 0.45 && j > i) ----
    for (int task = tid; task < KDET * 16; task += 1024) {
        int i = task >> 4;
        int w = task & 15;
        unsigned bits = 0;
        int jbase = w << 5;
        if (jbase + 31 > i) {
            float4 bi = S.boxes[i];
            float  ai = S.area[i];
            #pragma unroll 4
            for (int jj = 0; jj < 32; jj++) {
                int j = jbase + jj;
                if (j > i) {
                    float4 bj = S.boxes[j];
                    float xx1 = fmaxf(bi.x, bj.x), yy1 = fmaxf(bi.y, bj.y);
                    float xx2 = fminf(bi.z, bj.z), yy2 = fminf(bi.w, bj.w);
                    float iw = fmaxf(__fsub_rn(xx2, xx1), 0.f);
                    float ih = fmaxf(__fsub_rn(yy2, yy1), 0.f);
                    float inter = __fmul_rn(iw, ih);
                    // exact op order of ref: (ai + aj - inter) + 1e-7
                    float denom = __fadd_rn(__fsub_rn(__fadd_rn(ai, S.area[j]), inter), 1e-7f);
                    float t45 = __fmul_rn(denom, IOU_T);
                    bool over;
                    if      (inter > __fmul_rn(t45, 1.0000005f)) over = true;
                    else if (inter < __fmul_rn(t45, 0.9999995f)) over = false;
                    else    over = (__fdiv_rn(inter, denom) > IOU_T);  // exact path
                    if (over) bits |= (1u << jj);
                }
            }
        }
        S.mask[(i << 4) + w] = bits;
    }
    __syncthreads();

    // ---- Phase 7: greedy sequential suppression (thread 0, word-cached) ----
    if (tid == 0) {
        #pragma unroll
        for (int wb = 0; wb < 16; wb++) {
            unsigned rw = S.removed[wb];
            #pragma unroll 1
            for (int bit = 0; bit < 32; bit++) {
                if (!((rw >> bit) & 1u)) {
                    const int i = (wb << 5) + bit;   // box i is kept: suppress its row
                    const uint4* mr = (const uint4*)&S.mask[i << 4];
                    uint4* rm = (uint4*)S.removed;
                    uint4 a0 = mr[0], a1 = mr[1], a2 = mr[2], a3 = mr[3];
                    uint4 r0 = rm[0], r1 = rm[1], r2 = rm[2], r3 = rm[3];
                    r0.x |= a0.x; r0.y |= a0.y; r0.z |= a0.z; r0.w |= a0.w;
                    r1.x |= a1.x; r1.y |= a1.y; r1.z |= a1.z; r1.w |= a1.w;
                    r2.x |= a2.x; r2.y |= a2.y; r2.z |= a2.z; r2.w |= a2.w;
                    r3.x |= a3.x; r3.y |= a3.y; r3.z |= a3.z; r3.w |= a3.w;
                    rm[0] = r0; rm[1] = r1; rm[2] = r2; rm[3] = r3;
                    rw |= S.mask[(i << 4) + wb];     // keep local word current
                }
            }
        }
    }
    __syncthreads();

    // ---- Phase 8: write output [b, KDET, 9] ----
    if (tid < KDET) {
        bool kept = !((S.removed[tid >> 5] >> (tid & 31)) & 1u);
        float* orow = out + ((size_t)b * KDET + tid) * 9;
        if (kept) {
            float4 bx = S.boxes[tid];
            const float* r = pred + ((size_t)b * NPRED + S.sel_ix[tid]) * 9;
            orow[0] = bx.x; orow[1] = bx.y; orow[2] = bx.z; orow[3] = bx.w;
            orow[4] = S.sel_sc[tid];
            orow[5] = 0.0f;
            orow[6] = r[6]; orow[7] = r[7]; orow[8] = r[8];
        } else {
            #pragma unroll
            for (int q = 0; q < 9; q++) orow[q] = 0.0f;
        }
    }

    // ---- Phase 9: reset counter for next graph replay (deterministic) ----
    __syncthreads();
    if (tid == 0) g_cnt[b] = 0;
}

// ---------------------------------------------------------------------------
extern "C" void kernel_launch(void* const* d_in, const int* in_sizes, int n_in,
                              void* d_out, int out_size) {
    const float* pred = (const float*)d_in[0];
    float* out = (float*)d_out;

    // Pass 1: full-chip streaming score + compaction (DRAM-bound, ~35 us)
    score_compact_kernel<<<(NB * NPRED) / 256, 256>>>(pred);

    // Pass 2: per-batch select/sort/NMS (64 blocks, 1 per SM)
    cudaFuncSetAttribute(nms_kernel, cudaFuncAttributeMaxDynamicSharedMemorySize,
                         (int)sizeof(SmemB));
    nms_kernel<<<NB, 1024, sizeof(SmemB)>>>(pred, out);
}

// round 2
// speedup vs baseline: 2.2157x; 2.2157x over previous
#include <cuda_runtime.h>
#include <cstdint>
#include <cstddef>

#define NB      64
#define NPRED   100800
#define KDET    512
#define CAP     8192
#define SEL     1024
#define CONF_T  0.7f
#define IOU_T   0.45f

#define ROWS_PER_BLK 1024
#define BLKS_PER_B   99        // ceil(100800 / 1024)

// Global scratch (__device__ arrays: allowed; no allocation).
__device__ float g_sc[NB][CAP];
__device__ int   g_ix[NB][CAP];
__device__ int   g_cnt[NB];    // zero at load; reset by nms_kernel each replay

// ---------------------------------------------------------------------------
// Kernel 1: smem-staged coalesced scoring + two-level-aggregated compaction.
// Block = 256 threads, 1024 rows. All global loads are coalesced float4.
// ---------------------------------------------------------------------------
struct Smem1 {
    float tile[ROWS_PER_BLK * 9];   // 36 KB
    float stg_sc[256];
    int   stg_ix[256];
    int   sCnt;
    int   blockBase;
};

__global__ __launch_bounds__(256, 2)
void score_compact_kernel(const float* __restrict__ pred) {
    __shared__ Smem1 S;
    const int b   = blockIdx.y;
    const int tid = threadIdx.x;
    const int r0  = blockIdx.x * ROWS_PER_BLK;
    const int rows = min(ROWS_PER_BLK, NPRED - r0);
    const int nf4  = rows * 9 / 4;                 // 2304 or 1008 (both exact)

    // (b*NPRED + r0)*9 is divisible by 4 -> aligned float4 stream
    const float4* __restrict__ src =
        (const float4*)(pred + ((size_t)b * NPRED + r0) * 9);
    float4* dst = (float4*)S.tile;
    for (int q = tid; q < nf4; q += 256) dst[q] = src[q];
    if (tid == 0) S.sCnt = 0;
    __syncthreads();

    // conf from smem; addr (9r+4) mod 32: stride 9 coprime w/ 32 -> conflict-free
    #pragma unroll
    for (int k = 0; k < 4; k++) {
        int r = tid + 256 * k;
        if (r < rows) {
            float conf = __fmul_rn(S.tile[9 * r + 4], S.tile[9 * r + 5]);
            if (conf > CONF_T) {
                int p = atomicAdd(&S.sCnt, 1);      // ~52 per block
                if (p < 256) { S.stg_sc[p] = conf; S.stg_ix[p] = r0 + r; }
            }
        }
    }
    __syncthreads();
    if (tid == 0) S.blockBase = atomicAdd(&g_cnt[b], S.sCnt);  // ONE global atomic
    __syncthreads();

    int n = min(S.sCnt, 256);
    int base = S.blockBase;
    for (int t = tid; t < n; t += 256) {
        int p = base + t;
        if (p < CAP) { g_sc[b][p] = S.stg_sc[t]; g_ix[b][p] = S.stg_ix[t]; }
    }
}

// ---------------------------------------------------------------------------
// Kernel 2: per-batch radix-select + bitonic(1024) + ballot IoU mask +
//           register-resident greedy NMS + output.
// ---------------------------------------------------------------------------
struct __align__(16) SmemB {
    unsigned mask[KDET * 16];     // 32 KB  (16B-aligned rows of 64 B)
    float    sel_sc[SEL];         // 4 KB
    int      sel_ix[SEL];         // 4 KB
    float4   boxes[KDET];         // 8 KB
    float    area[KDET];          // 2 KB
    int      hist[1024];          // 4 KB
    unsigned kw[16];              // keep/removed words
    int      selCnt;
    int      b1;
};

__global__ __launch_bounds__(1024, 1)
void nms_kernel(const float* __restrict__ pred, float* __restrict__ out) {
    extern __shared__ SmemB s_[];
    SmemB& S = s_[0];
    const int tid  = threadIdx.x;
    const int lane = tid & 31;
    const int wid  = tid >> 5;
    const int b    = blockIdx.x;

    int cnt = g_cnt[b];
    if (cnt > CAP) cnt = CAP;

    // ---- Phase 1: histogram of score bits [22:13] (exp fixed for (0.7,1)) ----
    S.hist[tid] = 0;
    if (tid == 0) { S.selCnt = 0; S.b1 = -1; }
    __syncthreads();
    for (int e = tid; e < cnt; e += 1024) {
        unsigned u = __float_as_uint(g_sc[b][e]);
        atomicAdd(&S.hist[(u >> 13) & 1023], 1);
    }
    __syncthreads();

    // ---- Phase 2: suffix sum + boundary bin ----
    for (int d = 1; d < 1024; d <<= 1) {
        int v = (tid + d < 1024) ? S.hist[tid + d] : 0;
        __syncthreads();
        S.hist[tid] += v;
        __syncthreads();
    }
    int target = (cnt < KDET) ? cnt : KDET;
    if (S.hist[tid] >= target) atomicMax(&S.b1, tid);
    __syncthreads();
    int b1 = S.b1;

    // ---- Phase 3: collect bins >= b1 (~ target + bin spill) ----
    for (int e = tid; e < cnt; e += 1024) {
        float sc = g_sc[b][e];
        unsigned u = __float_as_uint(sc);
        if ((int)((u >> 13) & 1023) >= b1) {
            int p = atomicAdd(&S.selCnt, 1);
            if (p < SEL) { S.sel_sc[p] = sc; S.sel_ix[p] = g_ix[b][e]; }
        }
    }
    __syncthreads();
    int selN = S.selCnt; if (selN > SEL) selN = SEL;
    if (tid >= selN) { S.sel_sc[tid] = -1.0f; S.sel_ix[tid] = 0x7fffffff; }
    __syncthreads();

    // ---- Phase 4: bitonic sort 1024 (score desc, idx asc == lax.top_k order) ----
    for (int k = 2; k <= SEL; k <<= 1) {
        for (int j = k >> 1; j > 0; j >>= 1) {
            int t = tid, p = t ^ j;
            if (p > t) {
                float s1 = S.sel_sc[t], s2 = S.sel_sc[p];
                int   i1 = S.sel_ix[t], i2 = S.sel_ix[p];
                bool t_better = (s1 > s2) || (s1 == s2 && i1 < i2);
                if (t_better != ((t & k) == 0)) {
                    S.sel_sc[t] = s2; S.sel_sc[p] = s1;
                    S.sel_ix[t] = i2; S.sel_ix[p] = i1;
                }
            }
            __syncthreads();
        }
    }

    // ---- Phase 5: gather top-512 rows -> xyxy boxes, areas, validity words ----
    if (tid < KDET) {
        float sc = S.sel_sc[tid];
        float4 bx = make_float4(0.f, 0.f, 0.f, 0.f);
        float  ar = 0.f;
        bool valid = sc > CONF_T;
        if (valid) {
            const float* r = pred + ((size_t)b * NPRED + S.sel_ix[tid]) * 9;
            float cx = r[0], cy = r[1];
            float hw = __fmul_rn(r[2], 0.5f);      // exact; matches ref rounding
            float hh = __fmul_rn(r[3], 0.5f);
            bx.x = __fsub_rn(cx, hw); bx.y = __fsub_rn(cy, hh);
            bx.z = __fadd_rn(cx, hw); bx.w = __fadd_rn(cy, hh);
            ar = __fmul_rn(__fsub_rn(bx.z, bx.x), __fsub_rn(bx.w, bx.y));
        }
        S.boxes[tid] = bx;
        S.area[tid]  = ar;
        unsigned bal = __ballot_sync(0xffffffffu, valid);
        if (lane == 0) S.kw[wid] = ~bal;           // removed-init = !valid
    }
    __syncthreads();

    // ---- Phase 6: IoU mask via warp ballot: one warp-task = (row i, word w) ----
    for (int T = wid; T < KDET * 16; T += 32) {
        int i = T >> 4;
        int w = T & 15;
        unsigned bits = 0;
        if ((w << 5) + 31 > i) {                   // word contains some j > i
            float4 bi = S.boxes[i];                // LDS broadcast (N=1)
            float  ai = S.area[i];
            int    j  = (w << 5) + lane;           // lane owns box j in regs
            float4 bj = S.boxes[j];
            float  aj = S.area[j];
            float xx1 = fmaxf(bi.x, bj.x), yy1 = fmaxf(bi.y, bj.y);
            float xx2 = fminf(bi.z, bj.z), yy2 = fminf(bi.w, bj.w);
            float iw = fmaxf(__fsub_rn(xx2, xx1), 0.f);
            float ih = fmaxf(__fsub_rn(yy2, yy1), 0.f);
            float inter = __fmul_rn(iw, ih);
            // ref op order: (ai + aj - inter) + 1e-7
            float denom = __fadd_rn(__fsub_rn(__fadd_rn(ai, aj), inter), 1e-7f);
            float t45 = __fmul_rn(denom, IOU_T);
            bool over;
            if      (inter > __fmul_rn(t45, 1.0000005f)) over = true;
            else if (inter < __fmul_rn(t45, 0.9999995f)) over = false;
            else    over = (__fdiv_rn(inter, denom) > IOU_T);   // exact fallback
            bits = __ballot_sync(0xffffffffu, over && (j > i));
        }
        if (lane == 0) S.mask[T] = bits;
    }
    __syncthreads();

    // ---- Phase 7: greedy suppression, removed[] fully register-resident ----
    if (tid == 0) {
        unsigned rem[16];
        #pragma unroll
        for (int w = 0; w < 16; w++) rem[w] = S.kw[w];
        #pragma unroll 1
        for (int wb = 0; wb < 16; wb++) {
            unsigned alive = ~rem[wb];
            while (alive) {
                int bit = __ffs(alive) - 1;        // next still-kept box in word
                int i = (wb << 5) + bit;
                const uint4* mr = (const uint4*)&S.mask[i << 4];
                uint4 m0 = mr[0], m1 = mr[1], m2 = mr[2], m3 = mr[3];
                rem[0]  |= m0.x; rem[1]  |= m0.y; rem[2]  |= m0.z; rem[3]  |= m0.w;
                rem[4]  |= m1.x; rem[5]  |= m1.y; rem[6]  |= m1.z; rem[7]  |= m1.w;
                rem[8]  |= m2.x; rem[9]  |= m2.y; rem[10] |= m2.z; rem[11] |= m2.w;
                rem[12] |= m3.x; rem[13] |= m3.y; rem[14] |= m3.z; rem[15] |= m3.w;
                unsigned upper = (bit == 31) ? 0u : (0xffffffffu << (bit + 1));
                alive = ~rem[wb] & upper;          // i's own bit never set by mask
            }
        }
        #pragma unroll
        for (int w = 0; w < 16; w++) S.kw[w] = rem[w];
    }
    __syncthreads();

    // ---- Phase 8: write output [b, KDET, 9] ----
    if (tid < KDET) {
        bool kept = !((S.kw[tid >> 5] >> (tid & 31)) & 1u);
        float* orow = out + ((size_t)b * KDET + tid) * 9;
        if (kept) {
            float4 bx = S.boxes[tid];
            const float* r = pred + ((size_t)b * NPRED + S.sel_ix[tid]) * 9;
            orow[0] = bx.x; orow[1] = bx.y; orow[2] = bx.z; orow[3] = bx.w;
            orow[4] = S.sel_sc[tid];
            orow[5] = 0.0f;
            orow[6] = r[6]; orow[7] = r[7]; orow[8] = r[8];
        } else {
            #pragma unroll
            for (int q = 0; q < 9; q++) orow[q] = 0.0f;
        }
    }

    // ---- Phase 9: reset counter for next graph replay ----
    __syncthreads();
    if (tid == 0) g_cnt[b] = 0;
}

// ---------------------------------------------------------------------------
extern "C" void kernel_launch(void* const* d_in, const int* in_sizes, int n_in,
                              void* d_out, int out_size) {
    const float* pred = (const float*)d_in[0];
    float* out = (float*)d_out;

    dim3 g1(BLKS_PER_B, NB);
    score_compact_kernel<<<g1, 256>>>(pred);

    cudaFuncSetAttribute(nms_kernel, cudaFuncAttributeMaxDynamicSharedMemorySize,
                         (int)sizeof(SmemB));
    nms_kernel<<<NB, 1024, sizeof(SmemB)>>>(pred, out);
}

// round 3
// speedup vs baseline: 2.4908x; 1.1242x over previous
#include <cuda_runtime.h>
#include <cstdint>
#include <cstddef>

#define NB      64
#define NPRED   100800
#define KDET    512
#define CAP     8192
#define SEL     1024
#define CONF_T  0.7f
#define IOU_T   0.45f

#define ROWS_PER_BLK 1024
#define BLKS_PER_B   99        // ceil(100800 / 1024)

// Global scratch (__device__ arrays; no allocation).
__device__ float    g_sc[NB][CAP];
__device__ int      g_ix[NB][CAP];
__device__ int      g_cnt[NB];            // zero at load; reset by select_sort
__device__ float4   g_boxes[NB][KDET];
__device__ float    g_area[NB][KDET];
__device__ float    g_ssc[NB][KDET];
__device__ int      g_six[NB][KDET];
__device__ unsigned g_kw[NB][16];
__device__ unsigned g_mask[NB][KDET * 16];  // 2 MB

// ---------------------------------------------------------------------------
// Kernel 1: smem-staged coalesced scoring + two-level compaction.
// ---------------------------------------------------------------------------
__global__ __launch_bounds__(256)
void score_compact_kernel(const float* __restrict__ pred) {
    __shared__ float tile[ROWS_PER_BLK * 9];   // 36 KB
    __shared__ float stg_sc[256];
    __shared__ int   stg_ix[256];
    __shared__ int   sCnt, blockBase;

    const int b   = blockIdx.y;
    const int tid = threadIdx.x;
    const int r0  = blockIdx.x * ROWS_PER_BLK;
    const int rows = min(ROWS_PER_BLK, NPRED - r0);

    const float4* __restrict__ src =
        (const float4*)(pred + ((size_t)b * NPRED + r0) * 9);   // 16B-aligned
    float4* dst = (float4*)tile;
    if (rows == ROWS_PER_BLK) {
        #pragma unroll
        for (int u = 0; u < 9; u++) dst[tid + 256 * u] = src[tid + 256 * u];
    } else {
        int nf4 = rows * 9 / 4;                 // exact (448*9/4 = 1008)
        for (int q = tid; q < nf4; q += 256) dst[q] = src[q];
    }
    if (tid == 0) sCnt = 0;
    __syncthreads();

    #pragma unroll
    for (int k = 0; k < 4; k++) {
        int r = tid + 256 * k;
        if (r < rows) {
            float conf = __fmul_rn(tile[9 * r + 4], tile[9 * r + 5]);
            if (conf > CONF_T) {
                int p = atomicAdd(&sCnt, 1);
                if (p < 256) { stg_sc[p] = conf; stg_ix[p] = r0 + r; }
            }
        }
    }
    __syncthreads();
    if (tid == 0) blockBase = atomicAdd(&g_cnt[b], sCnt);   // ONE global atomic
    __syncthreads();

    int n = min(sCnt, 256);
    int base = blockBase;
    for (int t = tid; t < n; t += 256) {
        int p = base + t;
        if (p < CAP) { g_sc[b][p] = stg_sc[t]; g_ix[b][p] = stg_ix[t]; }
    }
}

// ---------------------------------------------------------------------------
// Kernel 2a: radix-select + hybrid register/shfl/smem bitonic(1024) + gather.
// ---------------------------------------------------------------------------
__global__ __launch_bounds__(1024, 1)
void select_sort_kernel(const float* __restrict__ pred) {
    __shared__ float bufS[2][SEL];     // 8 KB (double-buffer)
    __shared__ int   bufI[2][SEL];     // 8 KB
    __shared__ int   hist[1024];       // 4 KB
    __shared__ int   selCnt, b1s;

    const int tid = threadIdx.x;
    const int b   = blockIdx.x;
    int cnt = g_cnt[b];
    if (cnt > CAP) cnt = CAP;

    // Phase 1: histogram on score bits [22:13] (exponent fixed for (0.7,1))
    hist[tid] = 0;
    if (tid == 0) { selCnt = 0; b1s = -1; }
    __syncthreads();
    for (int e = tid; e < cnt; e += 1024) {
        unsigned u = __float_as_uint(g_sc[b][e]);
        atomicAdd(&hist[(u >> 13) & 1023], 1);
    }
    __syncthreads();

    // Phase 2: suffix sum + boundary bin
    for (int d = 1; d < 1024; d <<= 1) {
        int v = (tid + d < 1024) ? hist[tid + d] : 0;
        __syncthreads();
        hist[tid] += v;
        __syncthreads();
    }
    int target = (cnt < KDET) ? cnt : KDET;
    if (hist[tid] >= target) atomicMax(&b1s, tid);
    __syncthreads();
    int b1 = b1s;

    // Phase 3: collect bins >= b1 (~ target + boundary spill)
    for (int e = tid; e < cnt; e += 1024) {
        float sc = g_sc[b][e];
        if ((int)((__float_as_uint(sc) >> 13) & 1023) >= b1) {
            int p = atomicAdd(&selCnt, 1);
            if (p < SEL) { bufS[0][p] = sc; bufI[0][p] = g_ix[b][e]; }
        }
    }
    __syncthreads();
    int selN = selCnt; if (selN > SEL) selN = SEL;
    if (tid >= selN) { bufS[0][tid] = -1.0f; bufI[0][tid] = 0x7fffffff; }
    __syncthreads();

    // Phase 4: hybrid bitonic sort, one element per thread in registers.
    // (score desc, idx asc) == jax.lax.top_k order.
    float s  = bufS[0][tid];
    int   ix = bufI[0][tid];
    int   pb = 1;
    for (int k = 2; k <= SEL; k <<= 1) {
        for (int j = k >> 1; j > 0; j >>= 1) {
            float s2; int i2;
            if (j >= 32) {
                bufS[pb][tid] = s; bufI[pb][tid] = ix;
                __syncthreads();
                s2 = bufS[pb][tid ^ j]; i2 = bufI[pb][tid ^ j];
                pb ^= 1;
            } else {
                s2 = __shfl_xor_sync(0xffffffffu, s, j);
                i2 = __shfl_xor_sync(0xffffffffu, ix, j);
            }
            bool want_first = ((tid & k) == 0);   // block direction (desc-first)
            bool i_low      = ((tid & j) == 0);
            bool mine_better = (s > s2) || (s == s2 && ix < i2);
            if (mine_better != (i_low == want_first)) { s = s2; ix = i2; }
        }
    }

    // Phase 5: gather top-512 rows -> boxes/areas/validity, store to global.
    if (tid < KDET) {
        float4 bx = make_float4(0.f, 0.f, 0.f, 0.f);
        float  ar = 0.f;
        bool valid = s > CONF_T;
        if (valid) {
            const float* r = pred + ((size_t)b * NPRED + ix) * 9;
            float cx = r[0], cy = r[1];
            float hw = __fmul_rn(r[2], 0.5f);     // exact; matches ref rounding
            float hh = __fmul_rn(r[3], 0.5f);
            bx.x = __fsub_rn(cx, hw); bx.y = __fsub_rn(cy, hh);
            bx.z = __fadd_rn(cx, hw); bx.w = __fadd_rn(cy, hh);
            ar = __fmul_rn(__fsub_rn(bx.z, bx.x), __fsub_rn(bx.w, bx.y));
        }
        g_boxes[b][tid] = bx;
        g_area[b][tid]  = ar;
        g_ssc[b][tid]   = s;
        g_six[b][tid]   = ix;
        unsigned bal = __ballot_sync(0xffffffffu, valid);
        if ((tid & 31) == 0) g_kw[b][tid >> 5] = ~bal;  // removed-init = !valid
    }
    if (tid == 0) g_cnt[b] = 0;   // reset for next graph replay
}

// ---------------------------------------------------------------------------
// Kernel 2b: full-chip IoU suppression bitmask. One warp-task = (row i, word w).
// grid (16, NB) x 256 threads: 128 warps/batch, 64 tasks each.
// ---------------------------------------------------------------------------
__global__ __launch_bounds__(256)
void mask_kernel() {
    __shared__ float4 Sb[KDET];    // 8 KB
    __shared__ float  Sa[KDET];    // 2 KB
    const int tid  = threadIdx.x;
    const int lane = tid & 31;
    const int wid  = tid >> 5;
    const int b    = blockIdx.y;

    for (int q = tid; q < KDET; q += 256) { Sb[q] = g_boxes[b][q]; Sa[q] = g_area[b][q]; }
    __syncthreads();

    int wg = blockIdx.x * 8 + wid;             // 0..127 within batch
    for (int T = wg; T < KDET * 16; T += 128) {
        int i = T >> 4;
        int w = T & 15;
        unsigned bits = 0;
        if ((w << 5) + 31 > i) {               // word contains some j > i
            float4 bi = Sb[i];                 // LDS broadcast
            float  ai = Sa[i];
            int    j  = (w << 5) + lane;
            float4 bj = Sb[j];
            float  aj = Sa[j];
            float xx1 = fmaxf(bi.x, bj.x), yy1 = fmaxf(bi.y, bj.y);
            float xx2 = fminf(bi.z, bj.z), yy2 = fminf(bi.w, bj.w);
            float iw = fmaxf(__fsub_rn(xx2, xx1), 0.f);
            float ih = fmaxf(__fsub_rn(yy2, yy1), 0.f);
            float inter = __fmul_rn(iw, ih);
            float denom = __fadd_rn(__fsub_rn(__fadd_rn(ai, aj), inter), 1e-7f);
            float t45 = __fmul_rn(denom, IOU_T);
            bool over;
            if      (inter > __fmul_rn(t45, 1.0000005f)) over = true;
            else if (inter < __fmul_rn(t45, 0.9999995f)) over = false;
            else    over = (__fdiv_rn(inter, denom) > IOU_T);   // exact fallback
            bits = __ballot_sync(0xffffffffu, over && (j > i));
        }
        if (lane == 0) g_mask[b][T] = bits;
    }
}

// ---------------------------------------------------------------------------
// Kernel 2c: greedy sequential suppression (register-resident) + output.
// ---------------------------------------------------------------------------
__global__ __launch_bounds__(512)
void greedy_out_kernel(const float* __restrict__ pred, float* __restrict__ out) {
    __shared__ unsigned Sm[KDET * 16];   // 32 KB
    __shared__ unsigned Skw[16];
    const int tid = threadIdx.x;
    const int b   = blockIdx.x;

    {   // stage mask into smem, coalesced uint4
        const uint4* src = (const uint4*)g_mask[b];
        uint4* dst = (uint4*)Sm;
        #pragma unroll
        for (int u = 0; u < 4; u++) dst[tid + 512 * u] = src[tid + 512 * u];
    }
    if (tid < 16) Skw[tid] = g_kw[b][tid];
    __syncthreads();

    if (tid == 0) {
        unsigned rem[16];
        #pragma unroll
        for (int w = 0; w < 16; w++) rem[w] = Skw[w];
        #pragma unroll 1
        for (int wb = 0; wb < 16; wb++) {
            unsigned alive = ~rem[wb];
            while (alive) {
                int bit = __ffs(alive) - 1;
                int i = (wb << 5) + bit;
                const uint4* mr = (const uint4*)&Sm[i << 4];
                uint4 m0 = mr[0], m1 = mr[1], m2 = mr[2], m3 = mr[3];
                rem[0]  |= m0.x; rem[1]  |= m0.y; rem[2]  |= m0.z; rem[3]  |= m0.w;
                rem[4]  |= m1.x; rem[5]  |= m1.y; rem[6]  |= m1.z; rem[7]  |= m1.w;
                rem[8]  |= m2.x; rem[9]  |= m2.y; rem[10] |= m2.z; rem[11] |= m2.w;
                rem[12] |= m3.x; rem[13] |= m3.y; rem[14] |= m3.z; rem[15] |= m3.w;
                unsigned upper = (bit == 31) ? 0u : (0xffffffffu << (bit + 1));
                alive = ~rem[wb] & upper;
            }
        }
        #pragma unroll
        for (int w = 0; w < 16; w++) Skw[w] = rem[w];
    }
    __syncthreads();

    // Output [b, KDET, 9]
    bool kept = !((Skw[tid >> 5] >> (tid & 31)) & 1u);
    float* orow = out + ((size_t)b * KDET + tid) * 9;
    if (kept) {
        float4 bx = g_boxes[b][tid];
        const float* r = pred + ((size_t)b * NPRED + g_six[b][tid]) * 9;
        orow[0] = bx.x; orow[1] = bx.y; orow[2] = bx.z; orow[3] = bx.w;
        orow[4] = g_ssc[b][tid];
        orow[5] = 0.0f;
        orow[6] = r[6]; orow[7] = r[7]; orow[8] = r[8];
    } else {
        #pragma unroll
        for (int q = 0; q < 9; q++) orow[q] = 0.0f;
    }
}

// ---------------------------------------------------------------------------
extern "C" void kernel_launch(void* const* d_in, const int* in_sizes, int n_in,
                              void* d_out, int out_size) {
    const float* pred = (const float*)d_in[0];
    float* out = (float*)d_out;

    score_compact_kernel<<<dim3(BLKS_PER_B, NB), 256>>>(pred);
    select_sort_kernel<<<NB, 1024>>>(pred);
    mask_kernel<<<dim3(16, NB), 256>>>();
    greedy_out_kernel<<<NB, KDET>>>(pred, out);
}

// round 4
// speedup vs baseline: 3.2302x; 1.2968x over previous
#include <cuda_runtime.h>
#include <cstdint>
#include <cstddef>

#define NB      64
#define NPRED   100800
#define KDET    512
#define CAP     8192
#define SEL     1024
#define CONF_T  0.7f
#define IOU_T   0.45f

#define K1_THREADS 256
#define K1_RPT     8                    // rows per thread
#define K1_ROWS    (K1_THREADS * K1_RPT)   // 2048
#define K1_BLKS    50                   // 50*2048 = 102400 >= 100800

// Global scratch (__device__ arrays; no allocation).
__device__ float    g_sc[NB][CAP];
__device__ int      g_ix[NB][CAP];
__device__ int      g_cnt[NB];            // zero at load; reset by select_sort
__device__ float4   g_boxes[NB][KDET];
__device__ float    g_area[NB][KDET];
__device__ float    g_ssc[NB][KDET];
__device__ int      g_six[NB][KDET];
__device__ unsigned g_kw[NB][16];
__device__ unsigned g_mask[NB][KDET * 16];  // 2 MB

// ---------------------------------------------------------------------------
// Kernel 1: direct-LDG scoring + two-level compaction. DRAM-bound streamer.
// ---------------------------------------------------------------------------
__global__ __launch_bounds__(K1_THREADS)
void score_compact_kernel(const float* __restrict__ pred) {
    __shared__ float stg_sc[256];
    __shared__ int   stg_ix[256];
    __shared__ int   sCnt, blockBase;

    const int b   = blockIdx.y;
    const int tid = threadIdx.x;
    const int r0  = blockIdx.x * K1_ROWS;
    if (tid == 0) sCnt = 0;
    __syncthreads();

    const float* __restrict__ base = pred + (size_t)b * NPRED * 9;

    float a[K1_RPT], c[K1_RPT];
    int   rr[K1_RPT];
    #pragma unroll
    for (int k = 0; k < K1_RPT; k++) {          // front-batched loads (MLP 16)
        int r = r0 + k * K1_THREADS + tid;      // coalesced within each k
        rr[k] = r;
        bool ok = r < NPRED;
        const float* p = base + (size_t)r * 9;
        a[k] = ok ? __ldg(p + 4) : 0.0f;
        c[k] = ok ? __ldg(p + 5) : 0.0f;
    }
    #pragma unroll
    for (int k = 0; k < K1_RPT; k++) {
        float conf = __fmul_rn(a[k], c[k]);     // exact, matches reference
        if (conf > CONF_T) {
            int p = atomicAdd(&sCnt, 1);        // ~100 per block
            if (p < 256) { stg_sc[p] = conf; stg_ix[p] = rr[k]; }
        }
    }
    __syncthreads();
    if (tid == 0) blockBase = atomicAdd(&g_cnt[b], sCnt);   // ONE global atomic
    __syncthreads();

    int n = min(sCnt, 256);
    int gbase = blockBase;
    for (int t = tid; t < n; t += K1_THREADS) {
        int p = gbase + t;
        if (p < CAP) { g_sc[b][p] = stg_sc[t]; g_ix[b][p] = stg_ix[t]; }
    }
}

// ---------------------------------------------------------------------------
// Kernel 2a: radix-select + hybrid register/shfl/smem bitonic(1024) + gather.
// ---------------------------------------------------------------------------
__global__ __launch_bounds__(1024, 1)
void select_sort_kernel(const float* __restrict__ pred) {
    __shared__ float bufS[2][SEL];     // 8 KB (double-buffer)
    __shared__ int   bufI[2][SEL];     // 8 KB
    __shared__ int   hist[1024];       // 4 KB
    __shared__ int   selCnt, b1s;

    const int tid = threadIdx.x;
    const int b   = blockIdx.x;
    int cnt = g_cnt[b];
    if (cnt > CAP) cnt = CAP;

    // Phase 1: histogram on score bits [22:13] (exponent fixed for (0.7,1))
    hist[tid] = 0;
    if (tid == 0) { selCnt = 0; b1s = -1; }
    __syncthreads();
    for (int e = tid; e < cnt; e += 1024) {
        unsigned u = __float_as_uint(g_sc[b][e]);
        atomicAdd(&hist[(u >> 13) & 1023], 1);
    }
    __syncthreads();

    // Phase 2: suffix sum + boundary bin
    for (int d = 1; d < 1024; d <<= 1) {
        int v = (tid + d < 1024) ? hist[tid + d] : 0;
        __syncthreads();
        hist[tid] += v;
        __syncthreads();
    }
    int target = (cnt < KDET) ? cnt : KDET;
    if (hist[tid] >= target) atomicMax(&b1s, tid);
    __syncthreads();
    int b1 = b1s;

    // Phase 3: collect bins >= b1 (~ target + boundary spill)
    for (int e = tid; e < cnt; e += 1024) {
        float sc = g_sc[b][e];
        if ((int)((__float_as_uint(sc) >> 13) & 1023) >= b1) {
            int p = atomicAdd(&selCnt, 1);
            if (p < SEL) { bufS[0][p] = sc; bufI[0][p] = g_ix[b][e]; }
        }
    }
    __syncthreads();
    int selN = selCnt; if (selN > SEL) selN = SEL;
    if (tid >= selN) { bufS[0][tid] = -1.0f; bufI[0][tid] = 0x7fffffff; }
    __syncthreads();

    // Phase 4: hybrid bitonic sort (score desc, idx asc == lax.top_k order)
    float s  = bufS[0][tid];
    int   ix = bufI[0][tid];
    int   pb = 1;
    for (int k = 2; k <= SEL; k <<= 1) {
        for (int j = k >> 1; j > 0; j >>= 1) {
            float s2; int i2;
            if (j >= 32) {
                bufS[pb][tid] = s; bufI[pb][tid] = ix;
                __syncthreads();
                s2 = bufS[pb][tid ^ j]; i2 = bufI[pb][tid ^ j];
                pb ^= 1;
            } else {
                s2 = __shfl_xor_sync(0xffffffffu, s, j);
                i2 = __shfl_xor_sync(0xffffffffu, ix, j);
            }
            bool want_first = ((tid & k) == 0);
            bool i_low      = ((tid & j) == 0);
            bool mine_better = (s > s2) || (s == s2 && ix < i2);
            if (mine_better != (i_low == want_first)) { s = s2; ix = i2; }
        }
    }

    // Phase 5: gather top-512 rows -> boxes/areas/validity, store to global.
    if (tid < KDET) {
        float4 bx = make_float4(0.f, 0.f, 0.f, 0.f);
        float  ar = 0.f;
        bool valid = s > CONF_T;
        if (valid) {
            const float* r = pred + ((size_t)b * NPRED + ix) * 9;
            float cx = r[0], cy = r[1];
            float hw = __fmul_rn(r[2], 0.5f);     // exact; matches ref rounding
            float hh = __fmul_rn(r[3], 0.5f);
            bx.x = __fsub_rn(cx, hw); bx.y = __fsub_rn(cy, hh);
            bx.z = __fadd_rn(cx, hw); bx.w = __fadd_rn(cy, hh);
            ar = __fmul_rn(__fsub_rn(bx.z, bx.x), __fsub_rn(bx.w, bx.y));
        }
        g_boxes[b][tid] = bx;
        g_area[b][tid]  = ar;
        g_ssc[b][tid]   = s;
        g_six[b][tid]   = ix;
        unsigned bal = __ballot_sync(0xffffffffu, valid);
        if ((tid & 31) == 0) g_kw[b][tid >> 5] = ~bal;  // removed-init = !valid
    }
    if (tid == 0) g_cnt[b] = 0;   // reset for next graph replay
}

// ---------------------------------------------------------------------------
// Kernel 2b: full-chip IoU suppression bitmask. One warp-task = (row i, word w).
// ---------------------------------------------------------------------------
__global__ __launch_bounds__(256)
void mask_kernel() {
    __shared__ float4 Sb[KDET];    // 8 KB
    __shared__ float  Sa[KDET];    // 2 KB
    const int tid  = threadIdx.x;
    const int lane = tid & 31;
    const int wid  = tid >> 5;
    const int b    = blockIdx.y;

    for (int q = tid; q < KDET; q += 256) { Sb[q] = g_boxes[b][q]; Sa[q] = g_area[b][q]; }
    __syncthreads();

    int wg = blockIdx.x * 8 + wid;             // 0..127 within batch
    for (int T = wg; T < KDET * 16; T += 128) {
        int i = T >> 4;
        int w = T & 15;
        unsigned bits = 0;
        if ((w << 5) + 31 > i) {               // word contains some j > i
            float4 bi = Sb[i];                 // LDS broadcast
            float  ai = Sa[i];
            int    j  = (w << 5) + lane;
            float4 bj = Sb[j];
            float  aj = Sa[j];
            float xx1 = fmaxf(bi.x, bj.x), yy1 = fmaxf(bi.y, bj.y);
            float xx2 = fminf(bi.z, bj.z), yy2 = fminf(bi.w, bj.w);
            float iw = fmaxf(__fsub_rn(xx2, xx1), 0.f);
            float ih = fmaxf(__fsub_rn(yy2, yy1), 0.f);
            float inter = __fmul_rn(iw, ih);
            float denom = __fadd_rn(__fsub_rn(__fadd_rn(ai, aj), inter), 1e-7f);
            float t45 = __fmul_rn(denom, IOU_T);
            bool over;
            if      (inter > __fmul_rn(t45, 1.0000005f)) over = true;
            else if (inter < __fmul_rn(t45, 0.9999995f)) over = false;
            else    over = (__fdiv_rn(inter, denom) > IOU_T);   // exact fallback
            bits = __ballot_sync(0xffffffffu, over && (j > i));
        }
        if (lane == 0) g_mask[b][T] = bits;
    }
}

// ---------------------------------------------------------------------------
// Kernel 2c: warp-cooperative pipelined greedy suppression + output.
// ---------------------------------------------------------------------------
__global__ __launch_bounds__(512)
void greedy_out_kernel(const float* __restrict__ pred, float* __restrict__ out) {
    __shared__ unsigned Sm[KDET * 16];   // 32 KB
    __shared__ unsigned Skw[16];
    const int tid  = threadIdx.x;
    const int lane = tid & 31;
    const int b    = blockIdx.x;

    {   // stage mask into smem, coalesced uint4
        const uint4* src = (const uint4*)g_mask[b];
        uint4* dst = (uint4*)Sm;
        #pragma unroll
        for (int u = 0; u < 4; u++) dst[tid + 512 * u] = src[tid + 512 * u];
    }
    if (tid < 16) Skw[tid] = g_kw[b][tid];
    __syncthreads();

    // Warp 0: greedy scan. Lane l (mirrored at l+16) owns removed-word l&15.
    if (tid < 32) {
        const int l16 = lane & 15;
        unsigned rem = Skw[l16];
        const unsigned* rowp = Sm + l16;       // this lane's mask column
        #pragma unroll 1
        for (int wb = 0; wb < 16; wb++) {
            unsigned cur = __shfl_sync(0xffffffffu, rem, wb);  // word wb tracker
            const unsigned* curp = Sm + wb;
            const int ib = wb << 5;
            // depth-2 pipelined, always-load / conditionally-use
            unsigned prA = rowp[(ib + 0) << 4];
            unsigned pcA = curp[(ib + 0) << 4];
            unsigned prB = rowp[(ib + 1) << 4];
            unsigned pcB = curp[(ib + 1) << 4];
            #pragma unroll
            for (int bit = 0; bit < 32; bit++) {
                unsigned row = prA, cw = pcA;
                prA = prB; pcA = pcB;
                int nx = bit + 2; if (nx > 31) nx = 31;   // clamp inside word
                prB = rowp[(ib + nx) << 4];
                pcB = curp[(ib + nx) << 4];
                if (!((cur >> bit) & 1u)) {    // box ib+bit survives -> suppress
                    rem |= row;
                    cur |= cw;
                }
            }
        }
        if (lane < 16) Skw[lane] = rem;
    }
    __syncthreads();

    // Output [b, KDET, 9]
    bool kept = !((Skw[tid >> 5] >> (tid & 31)) & 1u);
    float* orow = out + ((size_t)b * KDET + tid) * 9;
    if (kept) {
        float4 bx = g_boxes[b][tid];
        const float* r = pred + ((size_t)b * NPRED + g_six[b][tid]) * 9;
        orow[0] = bx.x; orow[1] = bx.y; orow[2] = bx.z; orow[3] = bx.w;
        orow[4] = g_ssc[b][tid];
        orow[5] = 0.0f;
        orow[6] = r[6]; orow[7] = r[7]; orow[8] = r[8];
    } else {
        #pragma unroll
        for (int q = 0; q < 9; q++) orow[q] = 0.0f;
    }
}

// ---------------------------------------------------------------------------
extern "C" void kernel_launch(void* const* d_in, const int* in_sizes, int n_in,
                              void* d_out, int out_size) {
    const float* pred = (const float*)d_in[0];
    float* out = (float*)d_out;

    score_compact_kernel<<<dim3(K1_BLKS, NB), K1_THREADS>>>(pred);
    select_sort_kernel<<<NB, 1024>>>(pred);
    mask_kernel<<<dim3(16, NB), 256>>>();
    greedy_out_kernel<<<NB, KDET>>>(pred, out);
}